// round 14
// baseline (speedup 1.0000x reference)
#include <cuda_runtime.h>

// out[n, d, t] = mean over d' of in[n, d', t]
// in: [32768, 64, 64] fp32. Compulsory traffic: 512MB read + 512MB write.
//
// FINAL (champion, reproduced 3x: 169.3 / 168.7 / 168.4us): __ldcs + __stwt.
// Cache-policy matrix fully measured:
//   ld.cs + st.cs : 172.3-173.2us (5 runs)
//   ld.cs + st.wt : 168.4-169.3us <- best (write-through skips L2
//                                   write-allocate/dirty-writeback churn)
//   ld.cv + st.wt : 171.3us      (cv loses LTS read-combining)
// Structural variants all regress (persistent grid -4%, phase split -6%
// [pure-write drains at 73.9% < mixed 80%], half-threads/2x-footprint -34%);
// block 128/256/512 and unroll 8/16 neutral. TMA offers nothing: the LTS
// throughput cap (~6300 B/cyc) is path-independent on sm_103a.
// Kernel runs at the B300 mixed-stream memory roofline: 1.0737GB at
// ~6.7TB/s effective, issue 4.2%, all compute pipes idle.
//
// Layout: 2048 x 256 = 524288 threads (full latency-hiding complement),
// 16 threads/agent, one float4/thread, d-loop stride 256B ->
// fully-coalesced segments per half-warp.

static constexpr int N_AGENTS = 32768;
static constexpr int FEAT_DIM = 64;
static constexpr int QUADS_PER_ROW = 16;   // 64 t / 4
static constexpr int F4_PER_AGENT = 1024;  // 64*64/4

__global__ void __launch_bounds__(256)
mean_bcast_kernel(const float4* __restrict__ in, float4* __restrict__ out) {
    int gid = blockIdx.x * blockDim.x + threadIdx.x;   // 0 .. 32768*16-1
    int agent = gid >> 4;
    int tq = gid & 15;

    const float4* __restrict__ row = in + (size_t)agent * F4_PER_AGENT + tq;
    float4* __restrict__ orow = out + (size_t)agent * F4_PER_AGENT + tq;

    float ax = 0.f, ay = 0.f, az = 0.f, aw = 0.f;
    #pragma unroll 16
    for (int d = 0; d < FEAT_DIM; d++) {
        float4 v = __ldcs(&row[d * QUADS_PER_ROW]);
        ax += v.x; ay += v.y; az += v.z; aw += v.w;
    }
    const float inv = 1.0f / (float)FEAT_DIM;
    float4 m;
    m.x = ax * inv; m.y = ay * inv; m.z = az * inv; m.w = aw * inv;

    #pragma unroll 16
    for (int d = 0; d < FEAT_DIM; d++) {
        __stwt(&orow[d * QUADS_PER_ROW], m);
    }
}

extern "C" void kernel_launch(void* const* d_in, const int* in_sizes, int n_in,
                              void* d_out, int out_size) {
    const float4* in = (const float4*)d_in[0];
    float4* out = (float4*)d_out;
    // seq_start_end (d_in[1]) is a no-op: contiguous partition, mean is per-agent.
    int total_threads = N_AGENTS * QUADS_PER_ROW;   // 524288
    int block = 256;
    int grid = total_threads / block;               // 2048
    mean_bcast_kernel<<<grid, block>>>(in, out);
}

// round 15
// speedup vs baseline: 1.0059x; 1.0059x over previous
#include <cuda_runtime.h>

// out[n, d, t] = mean over d' of in[n, d', t]
// in: [32768, 64, 64] fp32. Compulsory: 512MB read + 512MB write.
//
// Champion so far: float4 + __ldcs/__stwt @ 2048x256 (168.4-169.3us, 4 runs).
// This round: Blackwell 256-bit vector ops (ld/st.global.v8.f32) — the one
// untested ISA knob. Full 524288-thread complement retained (R3/R6 proved
// occupancy is mandatory) by splitting the d-reduction: each thread owns an
// 8-float t-chunk and 32 of 64 d's; warp-partner (lane^8) combine via SHFL;
// each thread writes 32 d's with v8 stores. ld.cs (keep LTS read-combining),
// st.wt (skip write-allocate) per the measured cache-policy matrix.

static constexpr int N_AGENTS = 32768;
static constexpr int ROW_FLOATS = 64 * 64;   // 4096 floats per agent
static constexpr int T_DIM = 64;

__global__ void __launch_bounds__(256)
mean_bcast_kernel(const float* __restrict__ in, float* __restrict__ out) {
    int gid = blockIdx.x * blockDim.x + threadIdx.x;   // 0 .. 524287
    int agent = gid >> 4;
    int half  = (gid >> 3) & 1;   // which 32 d's this thread reduces/writes
    int chunk = gid & 7;          // which 8-float t-chunk

    const float* __restrict__ p =
        in + (size_t)agent * ROW_FLOATS + half * 32 * T_DIM + chunk * 8;
    float* __restrict__ q =
        out + (size_t)agent * ROW_FLOATS + half * 32 * T_DIM + chunk * 8;

    float a0 = 0.f, a1 = 0.f, a2 = 0.f, a3 = 0.f,
          a4 = 0.f, a5 = 0.f, a6 = 0.f, a7 = 0.f;

    #pragma unroll 8
    for (int d = 0; d < 32; d++) {
        float v0, v1, v2, v3, v4, v5, v6, v7;
        asm volatile(
            "ld.global.cs.v8.f32 {%0,%1,%2,%3,%4,%5,%6,%7}, [%8];"
            : "=f"(v0), "=f"(v1), "=f"(v2), "=f"(v3),
              "=f"(v4), "=f"(v5), "=f"(v6), "=f"(v7)
            : "l"(p + (size_t)d * T_DIM));
        a0 += v0; a1 += v1; a2 += v2; a3 += v3;
        a4 += v4; a5 += v5; a6 += v6; a7 += v7;
    }

    // Combine the two d-halves: partner lane is lane^8 (same warp).
    a0 += __shfl_xor_sync(0xffffffffu, a0, 8);
    a1 += __shfl_xor_sync(0xffffffffu, a1, 8);
    a2 += __shfl_xor_sync(0xffffffffu, a2, 8);
    a3 += __shfl_xor_sync(0xffffffffu, a3, 8);
    a4 += __shfl_xor_sync(0xffffffffu, a4, 8);
    a5 += __shfl_xor_sync(0xffffffffu, a5, 8);
    a6 += __shfl_xor_sync(0xffffffffu, a6, 8);
    a7 += __shfl_xor_sync(0xffffffffu, a7, 8);

    const float inv = 1.0f / 64.0f;
    a0 *= inv; a1 *= inv; a2 *= inv; a3 *= inv;
    a4 *= inv; a5 *= inv; a6 *= inv; a7 *= inv;

    #pragma unroll 8
    for (int d = 0; d < 32; d++) {
        asm volatile(
            "st.global.wt.v8.f32 [%0], {%1,%2,%3,%4,%5,%6,%7,%8};"
            :: "l"(q + (size_t)d * T_DIM),
               "f"(a0), "f"(a1), "f"(a2), "f"(a3),
               "f"(a4), "f"(a5), "f"(a6), "f"(a7)
            : "memory");
    }
}

extern "C" void kernel_launch(void* const* d_in, const int* in_sizes, int n_in,
                              void* d_out, int out_size) {
    const float* in = (const float*)d_in[0];
    float* out = (float*)d_out;
    // seq_start_end (d_in[1]) is a no-op: contiguous partition, mean is per-agent.
    int total_threads = N_AGENTS * 16;   // 524288 (full complement)
    int block = 256;
    int grid = total_threads / block;    // 2048
    mean_bcast_kernel<<<grid, block>>>(in, out);
}

// round 16
// speedup vs baseline: 1.0164x; 1.0104x over previous
#include <cuda_runtime.h>

// out[n, d, t] = mean over d' of in[n, d', t]
// in: [32768, 64, 64] fp32. Compulsory: 512MB read + 512MB write.
//
// R15 finding: 256-bit v8 ops beat float4 (167.7us, DRAM 80.6% — best BW of
// session) at only 53% occupancy -> bytes-in-flight, not occupancy, is the
// binding resource. This round deepens the in-flight window: load loop
// unroll 16 (512B outstanding/thread). Same thread layout: 16 threads/agent,
// each owns an 8-float t-chunk and 32 of 64 d's; lane^8 SHFL combine;
// v8 wt stores. ld.cs / st.wt per the measured cache-policy matrix.

static constexpr int N_AGENTS = 32768;
static constexpr int ROW_FLOATS = 64 * 64;   // 4096 floats per agent
static constexpr int T_DIM = 64;

__global__ void __launch_bounds__(256)
mean_bcast_kernel(const float* __restrict__ in, float* __restrict__ out) {
    int gid = blockIdx.x * blockDim.x + threadIdx.x;   // 0 .. 524287
    int agent = gid >> 4;
    int half  = (gid >> 3) & 1;   // which 32 d's this thread reduces/writes
    int chunk = gid & 7;          // which 8-float t-chunk

    const float* __restrict__ p =
        in + (size_t)agent * ROW_FLOATS + half * 32 * T_DIM + chunk * 8;
    float* __restrict__ q =
        out + (size_t)agent * ROW_FLOATS + half * 32 * T_DIM + chunk * 8;

    float a0 = 0.f, a1 = 0.f, a2 = 0.f, a3 = 0.f,
          a4 = 0.f, a5 = 0.f, a6 = 0.f, a7 = 0.f;

    #pragma unroll 16
    for (int d = 0; d < 32; d++) {
        float v0, v1, v2, v3, v4, v5, v6, v7;
        asm volatile(
            "ld.global.cs.v8.f32 {%0,%1,%2,%3,%4,%5,%6,%7}, [%8];"
            : "=f"(v0), "=f"(v1), "=f"(v2), "=f"(v3),
              "=f"(v4), "=f"(v5), "=f"(v6), "=f"(v7)
            : "l"(p + (size_t)d * T_DIM));
        a0 += v0; a1 += v1; a2 += v2; a3 += v3;
        a4 += v4; a5 += v5; a6 += v6; a7 += v7;
    }

    // Combine the two d-halves: partner lane is lane^8 (same warp).
    a0 += __shfl_xor_sync(0xffffffffu, a0, 8);
    a1 += __shfl_xor_sync(0xffffffffu, a1, 8);
    a2 += __shfl_xor_sync(0xffffffffu, a2, 8);
    a3 += __shfl_xor_sync(0xffffffffu, a3, 8);
    a4 += __shfl_xor_sync(0xffffffffu, a4, 8);
    a5 += __shfl_xor_sync(0xffffffffu, a5, 8);
    a6 += __shfl_xor_sync(0xffffffffu, a6, 8);
    a7 += __shfl_xor_sync(0xffffffffu, a7, 8);

    const float inv = 1.0f / 64.0f;
    a0 *= inv; a1 *= inv; a2 *= inv; a3 *= inv;
    a4 *= inv; a5 *= inv; a6 *= inv; a7 *= inv;

    #pragma unroll 8
    for (int d = 0; d < 32; d++) {
        asm volatile(
            "st.global.wt.v8.f32 [%0], {%1,%2,%3,%4,%5,%6,%7,%8};"
            :: "l"(q + (size_t)d * T_DIM),
               "f"(a0), "f"(a1), "f"(a2), "f"(a3),
               "f"(a4), "f"(a5), "f"(a6), "f"(a7)
            : "memory");
    }
}

extern "C" void kernel_launch(void* const* d_in, const int* in_sizes, int n_in,
                              void* d_out, int out_size) {
    const float* in = (const float*)d_in[0];
    float* out = (float*)d_out;
    // seq_start_end (d_in[1]) is a no-op: contiguous partition, mean is per-agent.
    int total_threads = N_AGENTS * 16;   // 524288
    int block = 256;
    int grid = total_threads / block;    // 2048
    mean_bcast_kernel<<<grid, block>>>(in, out);
}

// round 17
// speedup vs baseline: 1.0337x; 1.0171x over previous
#include <cuda_runtime.h>

// out[n, d, t] = mean over d' of in[n, d', t]
// in: [32768, 64, 64] fp32. Compulsory: 512MB read + 512MB write.
//
// Session model: bytes-in-flight is the binding resource (v8 @ 53% occ beat
// float4 @ 80% occ; deeper unroll gained again: 166.0us, DRAM 81.1%).
// At regs=48 ptxas can only keep ~4-5 v8 loads in flight (8 regs each) —
// the window is REGISTER-limited. This round: __launch_bounds__(256, 2)
// frees up to 128 regs/thread so the front-batched load window can ~double.
// Layout unchanged: 16 threads/agent, 8-float t-chunk, 32/64 d's per thread,
// lane^8 SHFL combine, ld.cs.v8 / st.wt.v8.

static constexpr int N_AGENTS = 32768;
static constexpr int ROW_FLOATS = 64 * 64;   // 4096 floats per agent
static constexpr int T_DIM = 64;

__global__ void __launch_bounds__(256, 2)
mean_bcast_kernel(const float* __restrict__ in, float* __restrict__ out) {
    int gid = blockIdx.x * blockDim.x + threadIdx.x;   // 0 .. 524287
    int agent = gid >> 4;
    int half  = (gid >> 3) & 1;   // which 32 d's this thread reduces/writes
    int chunk = gid & 7;          // which 8-float t-chunk

    const float* __restrict__ p =
        in + (size_t)agent * ROW_FLOATS + half * 32 * T_DIM + chunk * 8;
    float* __restrict__ q =
        out + (size_t)agent * ROW_FLOATS + half * 32 * T_DIM + chunk * 8;

    float a0 = 0.f, a1 = 0.f, a2 = 0.f, a3 = 0.f,
          a4 = 0.f, a5 = 0.f, a6 = 0.f, a7 = 0.f;

    #pragma unroll 16
    for (int d = 0; d < 32; d++) {
        float v0, v1, v2, v3, v4, v5, v6, v7;
        asm volatile(
            "ld.global.cs.v8.f32 {%0,%1,%2,%3,%4,%5,%6,%7}, [%8];"
            : "=f"(v0), "=f"(v1), "=f"(v2), "=f"(v3),
              "=f"(v4), "=f"(v5), "=f"(v6), "=f"(v7)
            : "l"(p + (size_t)d * T_DIM));
        a0 += v0; a1 += v1; a2 += v2; a3 += v3;
        a4 += v4; a5 += v5; a6 += v6; a7 += v7;
    }

    // Combine the two d-halves: partner lane is lane^8 (same warp).
    a0 += __shfl_xor_sync(0xffffffffu, a0, 8);
    a1 += __shfl_xor_sync(0xffffffffu, a1, 8);
    a2 += __shfl_xor_sync(0xffffffffu, a2, 8);
    a3 += __shfl_xor_sync(0xffffffffu, a3, 8);
    a4 += __shfl_xor_sync(0xffffffffu, a4, 8);
    a5 += __shfl_xor_sync(0xffffffffu, a5, 8);
    a6 += __shfl_xor_sync(0xffffffffu, a6, 8);
    a7 += __shfl_xor_sync(0xffffffffu, a7, 8);

    const float inv = 1.0f / 64.0f;
    a0 *= inv; a1 *= inv; a2 *= inv; a3 *= inv;
    a4 *= inv; a5 *= inv; a6 *= inv; a7 *= inv;

    #pragma unroll 8
    for (int d = 0; d < 32; d++) {
        asm volatile(
            "st.global.wt.v8.f32 [%0], {%1,%2,%3,%4,%5,%6,%7,%8};"
            :: "l"(q + (size_t)d * T_DIM),
               "f"(a0), "f"(a1), "f"(a2), "f"(a3),
               "f"(a4), "f"(a5), "f"(a6), "f"(a7)
            : "memory");
    }
}

extern "C" void kernel_launch(void* const* d_in, const int* in_sizes, int n_in,
                              void* d_out, int out_size) {
    const float* in = (const float*)d_in[0];
    float* out = (float*)d_out;
    // seq_start_end (d_in[1]) is a no-op: contiguous partition, mean is per-agent.
    int total_threads = N_AGENTS * 16;   // 524288
    int block = 256;
    int grid = total_threads / block;    // 2048
    mean_bcast_kernel<<<grid, block>>>(in, out);
}